// round 10
// baseline (speedup 1.0000x reference)
#include <cuda_runtime.h>

// SegGPS_66949950210076
// out[b] = sum_m prod_l eps[idx[b,l], m, l, nup[b,l], ndn[b,l]]
// B=8192, L=64, M=64, LOCAL_DIM=4, eps (4,64,64,65,65) fp32.
//
// R7: 3 kernels. flag (mark touched cells) -> transpose (warp-per-idx,
// ballot-driven, self-clearing flags, no smem/sync) -> gather (warp/batch,
// float4 lane-split). T[cell][idx][m] m-contiguous 256B blocks, L2-resident.
// Index dtype (int32 vs int64) self-detected per warp from a probe window.

#define B_SZ   8192
#define L_SZ   64
#define IDX_STRIDE 17305600   // M*L*65*65
#define M_STRIDE   270400     // L*65*65
#define L_STRIDE   4225       // 65*65
#define CELLS  89440          // sum_{k=1..64} k^2
#define T_ELEMS (CELLS * 256)

__device__ __align__(256) float g_T[T_ELEMS]; // 91.6 MB scratch (static)
__device__ unsigned char g_flags[4][CELLS];   // zero-init; transpose self-clears

__device__ __forceinline__ int cell_off(int l) {
    return l * (l + 1) * (2 * l + 1) / 6;     // sum_{j=1..l} j^2
}
__device__ __forceinline__ float4 mul4(float4 a, float4 b) {
    return make_float4(a.x * b.x, a.y * b.y, a.z * b.z, a.w * b.w);
}

// Per-warp dtype probe. Indices are logically int64 (ref) but JAX x64-off
// emits int32. Under int64 LE every odd 32-bit word of the buffer is 0
// (values < 4); under int32 odd words are random in [0,4).
// Probe 64 odd words of a fixed 128-word window inside the first 524288
// words (in-bounds under either dtype: base+127 <= 524287).
// P(false int64 | int32 data) = 0.25^64 per warp.
__device__ __forceinline__ int probe_is_int32(const unsigned* __restrict__ w,
                                              int b, int lane) {
    int base = (b & 4095) * 128;
    unsigned x = w[base + 2 * lane + 1] | w[base + 64 + 2 * lane + 1];
    return __ballot_sync(0xffffffffu, x != 0u) != 0u;
}

// Per-warp scan of one batch: two ballots cover all 64 sites.
__device__ __forceinline__ void scan_batch(
    const void* idx_raw, int is32, int b, int lane,
    int& v0, int& v1, int& cell0, int& cell1)
{
    if (is32) {
        const int* p = (const int*)idx_raw + b * L_SZ;
        v0 = p[lane];  v1 = p[lane + 32];
    } else {
        const long long* p = (const long long*)idx_raw + (size_t)b * L_SZ;
        v0 = (int)p[lane];  v1 = (int)p[lane + 32];
    }
    unsigned bu0 = __ballot_sync(0xffffffffu, v0 & 1);
    unsigned bd0 = __ballot_sync(0xffffffffu, v0 & 2);
    unsigned bu1 = __ballot_sync(0xffffffffu, v1 & 1);
    unsigned bd1 = __ballot_sync(0xffffffffu, v1 & 2);
    unsigned mlt = (1u << lane) - 1u;
    int nup0 = __popc(bu0 & mlt),               ndn0 = __popc(bd0 & mlt);
    int nup1 = __popc(bu0) + __popc(bu1 & mlt), ndn1 = __popc(bd0) + __popc(bd1 & mlt);
    cell0 = cell_off(lane)      + nup0 * (lane + 1)  + ndn0;
    cell1 = cell_off(lane + 32) + nup1 * (lane + 33) + ndn1;
}

// ---- mark touched cells ----
__global__ __launch_bounds__(256) void flag_kernel(const void* __restrict__ idx_raw) {
    int lane = threadIdx.x & 31;
    int b = blockIdx.x * 8 + (threadIdx.x >> 5);
    int is32 = probe_is_int32((const unsigned*)idx_raw, b, lane);
    int v0, v1, c0, c1;
    scan_batch(idx_raw, is32, b, lane, v0, v1, c0, c1);
    g_flags[v0][c0] = 1;
    g_flags[v1][c1] = 1;
}

// ---- transpose: CTA(128) per (l,nup); warp = idx; ballot over cells ----
__global__ __launch_bounds__(128) void transpose_kernel(const float* __restrict__ eps) {
    const int l = blockIdx.x, nup = blockIdx.y;
    if (nup > l) return;
    const int nv = l + 1;
    const int cellbase = cell_off(l) + nup * nv;

    const int lane = threadIdx.x & 31;
    const int idx  = threadIdx.x >> 5;       // warp = idx value 0..3

    unsigned char* fl = &g_flags[idx][cellbase];
    int f0 = (lane < nv)      ? fl[lane]      : 0;
    int f1 = (lane + 32 < nv) ? fl[lane + 32] : 0;
    unsigned b0 = __ballot_sync(0xffffffffu, f0);
    unsigned b1 = __ballot_sync(0xffffffffu, f1);
    if (f0) fl[lane]      = 0;               // restore all-zero invariant
    if (f1) fl[lane + 32] = 0;

    unsigned long long m = (unsigned long long)b0
                         | ((unsigned long long)b1 << 32);
    if (!m) return;

    const float* src = eps + idx * IDX_STRIDE + l * L_STRIDE + nup * 65;
    const float* s0 = src + lane * M_STRIDE;          // m = lane
    const float* s1 = src + (lane + 32) * M_STRIDE;   // m = lane+32
    float* dstbase = g_T + (size_t)cellbase * 256 + idx * 64;

    while (m) {
        int n0 = __ffsll(m) - 1;  m &= m - 1;
        int n1 = -1;
        if (m) { n1 = __ffsll(m) - 1;  m &= m - 1; }
        // 2-4 independent loads in flight per iteration
        float a0 = __ldg(s0 + n0);
        float a1 = __ldg(s1 + n0);
        float c0 = 0.f, c1 = 0.f;
        if (n1 >= 0) { c0 = __ldg(s0 + n1); c1 = __ldg(s1 + n1); }
        float* d0 = dstbase + n0 * 256;
        d0[lane]      = a0;                  // 256B coalesced per cell
        d0[lane + 32] = a1;
        if (n1 >= 0) {
            float* d1 = dstbase + n1 * 256;
            d1[lane]      = c0;
            d1[lane + 32] = c1;
        }
    }
}

// ---- gather: warp per batch; float4, lane-split (even/odd sites) ----
__global__ __launch_bounds__(256) void seggps_kernel(
    const void* __restrict__ idx_raw,
    float*      __restrict__ out)
{
    __shared__ int soffs[8][64];

    const int lane = threadIdx.x & 31;
    const int w    = threadIdx.x >> 5;
    const int b    = blockIdx.x * 8 + w;

    int is32 = probe_is_int32((const unsigned*)idx_raw, b, lane);
    int v0, v1, c0, c1;
    scan_batch(idx_raw, is32, b, lane, v0, v1, c0, c1);
    soffs[w][lane]      = c0 * 256 + v0 * 64;
    soffs[w][lane + 32] = c1 * 256 + v1 * 64;
    __syncwarp();

    // lanes 0-15: even sites; lanes 16-31: odd sites. q = m-quad (4 floats).
    const int half = lane >> 4;
    const int q    = lane & 15;

    float4 a0 = make_float4(1.f, 1.f, 1.f, 1.f), a1 = a0, a2 = a0, a3 = a0;
    #pragma unroll
    for (int i = 0; i < 32; i += 4) {
        float4 x0 = __ldg((const float4*)(g_T + soffs[w][2 * (i + 0) + half]) + q);
        float4 x1 = __ldg((const float4*)(g_T + soffs[w][2 * (i + 1) + half]) + q);
        float4 x2 = __ldg((const float4*)(g_T + soffs[w][2 * (i + 2) + half]) + q);
        float4 x3 = __ldg((const float4*)(g_T + soffs[w][2 * (i + 3) + half]) + q);
        a0 = mul4(a0, x0);
        a1 = mul4(a1, x1);
        a2 = mul4(a2, x2);
        a3 = mul4(a3, x3);
    }
    float4 p = mul4(mul4(a0, a1), mul4(a2, a3));   // this half's product

    // combine halves: lane j and j+16 both get full product of quad j
    float4 o;
    o.x = __shfl_xor_sync(0xffffffffu, p.x, 16);
    o.y = __shfl_xor_sync(0xffffffffu, p.y, 16);
    o.z = __shfl_xor_sync(0xffffffffu, p.z, 16);
    o.w = __shfl_xor_sync(0xffffffffu, p.w, 16);
    p = mul4(p, o);

    float s = (p.x + p.y) + (p.z + p.w);           // sum over quad's 4 m
    #pragma unroll
    for (int off = 8; off; off >>= 1) s += __shfl_xor_sync(0xffffffffu, s, off);
    if (lane == 0) out[b] = s;                     // sum over quads 0..15
}

extern "C" void kernel_launch(void* const* d_in, const int* in_sizes, int n_in,
                              void* d_out, int out_size)
{
    const void*  idx = d_in[0];                 // indices (B,L) int32 or int64
    const float* eps = (const float*)d_in[1];   // epsilon fp32
    float* out = (float*)d_out;
    (void)in_sizes; (void)n_in; (void)out_size;

    flag_kernel<<<B_SZ / 8, 256>>>(idx);
    transpose_kernel<<<dim3(64, 64), 128>>>(eps);
    seggps_kernel<<<B_SZ / 8, 256>>>(idx, out);
}